// round 6
// baseline (speedup 1.0000x reference)
#include <cuda_runtime.h>

#define W_      10
#define NSTATE  4096
#define BATCH   512
#define NIN     6
#define STAGES  2

// g_tab[(s*W + out)*1024 + g] = (cos(phi/2), sin(phi/2)); g = state bits 11..2
__device__ float2 g_tab[STAGES * W_ * 1024];
__device__ float2 u_tab[STAGES * W_];

__global__ void precompute_kernel(const float* __restrict__ unitary_theta,
                                  const float* __restrict__ neuron_theta) {
    int idx = blockIdx.x * blockDim.x + threadIdx.x;
    if (idx < STAGES * W_ * 1024) {
        int g  = idx & 1023;
        int sn = idx >> 10;
        const float* th = neuron_theta + sn * (W_ + 1);
        float phi = th[W_];
        #pragma unroll
        for (int i = 0; i < W_; i++)
            if ((g >> (9 - i)) & 1) phi += th[i];
        float sv, cv;
        sincosf(phi * 0.5f, &sv, &cv);
        g_tab[idx] = make_float2(cv, sv);
    }
    if (idx < STAGES * W_) {
        float sv, cv;
        sincosf(unitary_theta[idx] * 0.5f, &sv, &cv);
        u_tab[idx] = make_float2(cv, sv);
    }
}

// ---- swizzle on float4-group index: conflict-free for all 6 sweep patterns
__device__ __forceinline__ int sg(int G) {
    int b = (((G >> 3) ^ (G >> 6)) & 1)
          | ((((G >> 4) ^ (G >> 7)) & 1) << 1)
          | (((G >> 5) & 1) << 2);
    return G ^ b;
}
__device__ __forceinline__ int sf(int i) { return (sg(i >> 2) << 2) | (i & 3); }

// ---- scalar gate primitives (R4-proven) ----
__device__ __forceinline__ void grp4(float4& a, float c, float s, float sgn) {
    float t0 = c * a.x - s * a.z;
    float t1 = c * a.y - s * a.w;
    float t2 = s * a.x + c * a.z;
    float t3 = s * a.y + c * a.w;
    float u2 = -sgn * t3, u3 = sgn * t2;
    a.x =  c * t0 + s * u2;
    a.y =  c * t1 + s * u3;
    a.z = -s * t0 + c * u2;
    a.w = -s * t1 + c * u3;
}
// full neuron on 8 amps: A0 = target-bit=0 group, A1 = target-bit=1 group
__device__ __forceinline__ void neuron8(float4& A0, float4& A1, float2 cs0, float2 cs1) {
    grp4(A0, cs0.x, cs0.y, 1.f);
    grp4(A1, cs1.x, cs1.y, 1.f);
    float x1 = A0.y; A0.y = -A1.y; A1.y = x1;
    float x3 = A0.w; A0.w = -A1.w; A1.w = x3;
    grp4(A0, cs0.x, cs0.y, -1.f);
    grp4(A1, cs1.x, cs1.y, -1.f);
}
// RY on bit b of the 32-element register index k
__device__ __forceinline__ void ry32(float r[32], int b, float2 cs) {
    #pragma unroll
    for (int k = 0; k < 32; k++) {
        if (!((k >> b) & 1)) {
            int k1 = k | (1 << b);
            float a0 = r[k], a1 = r[k1];
            r[k]  = cs.x * a0 - cs.y * a1;
            r[k1] = cs.y * a0 + cs.x * a1;
        }
    }
}

// Neuron triple on 8 owned groups. m-bit2 = first neuron's target, bit1, bit0 next.
__device__ __forceinline__ void neuron_triple(float4* st4, const int G[8],
                                              const float2* __restrict__ tb0,
                                              const float2* __restrict__ tb1,
                                              const float2* __restrict__ tb2) {
    float4 q[8];
    #pragma unroll
    for (int m = 0; m < 8; m++) q[m] = st4[sg(G[m])];
    #pragma unroll
    for (int m = 0; m < 4; m++) neuron8(q[m], q[m + 4], tb0[G[m]], tb0[G[m + 4]]);
    neuron8(q[0], q[2], tb1[G[0]], tb1[G[2]]);
    neuron8(q[1], q[3], tb1[G[1]], tb1[G[3]]);
    neuron8(q[4], q[6], tb1[G[4]], tb1[G[6]]);
    neuron8(q[5], q[7], tb1[G[5]], tb1[G[7]]);
    #pragma unroll
    for (int m = 0; m < 8; m += 2) neuron8(q[m], q[m + 1], tb2[G[m]], tb2[G[m + 1]]);
    #pragma unroll
    for (int m = 0; m < 8; m++) st4[sg(G[m])] = q[m];
}

__global__ void __launch_bounds__(128) sim_kernel(
    const float* __restrict__ psi_in,
    const int*   __restrict__ inp,
    float*       __restrict__ probs_out,
    float*       __restrict__ psi_out)
{
    __shared__ __align__(16) float st[NSTATE];
    __shared__ float red[128];
    float4* st4 = (float4*)st;

    const int b = blockIdx.x;
    const int t = threadIdx.x;

    int mask = 0;
    #pragma unroll
    for (int l = 0; l < NIN; l++) mask |= (inp[l] & 1) << (11 - l);

    #pragma unroll
    for (int s = 0; s < STAGES; s++) {
        const float2* ut = &u_tab[s * W_];

        // ---- U1: RY lanes 0-4 (amp bits 11..7). amp = t | (k<<7).
        {
            float r[32];
            if (s == 0) {
                const float* in = psi_in + (size_t)b * NSTATE;
                #pragma unroll
                for (int k = 0; k < 32; k++) r[k] = in[(t | (k << 7)) ^ mask];
            } else {
                #pragma unroll
                for (int k = 0; k < 32; k++) r[k] = st[sf(t | (k << 7))];
            }
            ry32(r, 4, ut[0]); ry32(r, 3, ut[1]); ry32(r, 2, ut[2]);
            ry32(r, 1, ut[3]); ry32(r, 0, ut[4]);
            #pragma unroll
            for (int k = 0; k < 32; k++) st[sf(t | (k << 7))] = r[k];
        }
        __syncthreads();

        // ---- U2: RY lanes 5-9 (amp bits 6..2). amp = (t&3)|((t>>2)<<7)|(k<<2).
        {
            const int base = (t & 3) | ((t >> 2) << 7);
            float r[32];
            #pragma unroll
            for (int k = 0; k < 32; k++) r[k] = st[sf(base | (k << 2))];
            ry32(r, 4, ut[5]); ry32(r, 3, ut[6]); ry32(r, 2, ut[7]);
            ry32(r, 1, ut[8]); ry32(r, 0, ut[9]);
            #pragma unroll
            for (int k = 0; k < 32; k++) st[sf(base | (k << 2))] = r[k];
        }
        __syncthreads();

        const float2* tb = &g_tab[(s * W_) << 10];

        // ---- A: neurons 0,1,2 (group bits 9,8,7). G = t | (m<<7).
        {
            int G[8];
            #pragma unroll
            for (int m = 0; m < 8; m++) G[m] = t | (m << 7);
            neuron_triple(st4, G, tb + (0 << 10), tb + (1 << 10), tb + (2 << 10));
        }
        __syncthreads();

        // ---- B: neurons 3,4,5 (group bits 6,5,4). G = (t&15)|(m<<4)|((t>>4)<<7).
        {
            const int gb = (t & 15) | ((t >> 4) << 7);
            int G[8];
            #pragma unroll
            for (int m = 0; m < 8; m++) G[m] = gb | (m << 4);
            neuron_triple(st4, G, tb + (3 << 10), tb + (4 << 10), tb + (5 << 10));
        }
        __syncthreads();

        // ---- C: neurons 6,7,8 (group bits 3,2,1). G = (t&1)|(m<<1)|((t>>1)<<4).
        {
            const int gb = (t & 1) | ((t >> 1) << 4);
            int G[8];
            #pragma unroll
            for (int m = 0; m < 8; m++) G[m] = gb | (m << 1);
            neuron_triple(st4, G, tb + (6 << 10), tb + (7 << 10), tb + (8 << 10));
        }
        __syncthreads();

        // ---- D: neuron 9 (group bit 0). 8 contiguous groups G = (t<<3)+m.
        {
            const float2* t9 = tb + (9 << 10);
            const int G0 = t << 3;
            float4 q[8];
            #pragma unroll
            for (int m = 0; m < 8; m++) q[m] = st4[sg(G0 + m)];
            #pragma unroll
            for (int m = 0; m < 8; m += 2)
                neuron8(q[m], q[m + 1], t9[G0 + m], t9[G0 + m + 1]);

            if (s == STAGES - 1) {
                float4* out4 = (float4*)(psi_out + (size_t)b * NSTATE);
                float ssq = 0.f;
                #pragma unroll
                for (int m = 0; m < 8; m++) {
                    out4[G0 + m] = q[m];
                    ssq += q[m].x * q[m].x + q[m].y * q[m].y
                         + q[m].z * q[m].z + q[m].w * q[m].w;
                }
                red[t] = ssq;
            } else {
                #pragma unroll
                for (int m = 0; m < 8; m++) st4[sg(G0 + m)] = q[m];
            }
        }
        __syncthreads();
    }

    // probs: bucket = amp bits 11..6 = t>>1 for thread t's 32 contiguous amps
    if (t < 64) {
        probs_out[b * 64 + t] = red[2 * t] + red[2 * t + 1];
    }
}

extern "C" void kernel_launch(void* const* d_in, const int* in_sizes, int n_in,
                              void* d_out, int out_size) {
    const float* psi = (const float*)d_in[0];
    const int*   inp = (const int*)d_in[1];
    const float* uth = (const float*)d_in[2];
    const float* nth = (const float*)d_in[3];
    float* out = (float*)d_out;

    float* probs_out = out;
    float* psi_out   = out + BATCH * 64;

    precompute_kernel<<<(STAGES * W_ * 1024 + 255) / 256, 256>>>(uth, nth);
    sim_kernel<<<BATCH, 128>>>(psi, inp, probs_out, psi_out);
}

// round 7
// speedup vs baseline: 1.1746x; 1.1746x over previous
#include <cuda_runtime.h>

#define W_      10
#define NSTATE  4096
#define BATCH   512
#define NIN     6
#define STAGES  2

typedef unsigned long long u64;

#define NEGB   0x8000000080000000ULL
#define MASKP  0x0000000080000000ULL
#define MASKM  0x8000000000000000ULL

// g_tab[(s*W + out)*1024 + g] = (cos(phi/2), sin(phi/2)); g = amp bits 11..2
__device__ float2 g_tab[STAGES * W_ * 1024];
__device__ float2 u_tab[STAGES * W_];

__global__ void precompute_kernel(const float* __restrict__ unitary_theta,
                                  const float* __restrict__ neuron_theta) {
    int idx = blockIdx.x * blockDim.x + threadIdx.x;
    if (idx < STAGES * W_ * 1024) {
        int g  = idx & 1023;
        int sn = idx >> 10;
        const float* th = neuron_theta + sn * (W_ + 1);
        float phi = th[W_];
        #pragma unroll
        for (int i = 0; i < W_; i++)
            if ((g >> (9 - i)) & 1) phi += th[i];
        float sv, cv;
        sincosf(phi * 0.5f, &sv, &cv);
        g_tab[idx] = make_float2(cv, sv);
    }
    if (idx < STAGES * W_) {
        float sv, cv;
        sincosf(unitary_theta[idx] * 0.5f, &sv, &cv);
        u_tab[idx] = make_float2(cv, sv);
    }
}

// ---- f32x2 primitives (R5-proven) ----
__device__ __forceinline__ u64 pk2(float lo, float hi) {
    u64 r; asm("mov.b64 %0, {%1,%2};" : "=l"(r) : "f"(lo), "f"(hi)); return r;
}
__device__ __forceinline__ u64 bcast(float v) { return pk2(v, v); }
__device__ __forceinline__ u64 f2mul(u64 a, u64 b) {
    u64 r; asm("mul.rn.f32x2 %0, %1, %2;" : "=l"(r) : "l"(a), "l"(b)); return r;
}
__device__ __forceinline__ u64 f2fma(u64 a, u64 b, u64 c) {
    u64 r; asm("fma.rn.f32x2 %0, %1, %2, %3;" : "=l"(r) : "l"(a), "l"(b), "l"(c)); return r;
}
__device__ __forceinline__ u64 lswap(u64 a) {
    u64 r; asm("{.reg .b32 x,y; mov.b64 {x,y}, %1; mov.b64 %0, {y,x};}" : "=l"(r) : "l"(a)); return r;
}
// A.hi_new = -B.hi_old ; B.hi_new = A.hi_old
__device__ __forceinline__ void xswapneg(u64& a, u64& b) {
    asm("{\n\t.reg .b32 al,ah,bl,bh;\n\t"
        "mov.b64 {al,ah}, %0;\n\t"
        "mov.b64 {bl,bh}, %1;\n\t"
        "neg.f32 bh, bh;\n\t"
        "mov.b64 %0, {al,bh};\n\t"
        "mov.b64 %1, {bl,ah};\n\t}"
        : "+l"(a), "+l"(b));
}

// ---- swizzle on float4-group index G = amp>>2 (hand-verified conflict-free
// per wavefront for all 8 sweep patterns)
__device__ __forceinline__ int swG(int G) {
    return G ^ ( ((G >> 3) & 1)
               | (((G >> 4) & 1) << 1)
               | ((((G >> 5) ^ (G >> 4)) & 1) << 2) );
}
// u64 element index e = amp>>1 (lo lane q11=0, hi q11=1; e bit0 = q10)
__device__ __forceinline__ int swE(int e) { return (swG(e >> 1) << 1) | (e & 1); }

__device__ __forceinline__ void ld2(const u64* sm, int g, u64& a, u64& b) {
    ulonglong2 v = *(const ulonglong2*)(sm + (swG(g) << 1)); a = v.x; b = v.y;
}
__device__ __forceinline__ void st2(u64* sm, int g, u64 a, u64 b) {
    *(ulonglong2*)(sm + (swG(g) << 1)) = make_ulonglong2(a, b);
}

// grp4 packed (R5-proven): RY(+phi) q10, CRY(sgn*pi) 10->11, RY(-phi) q10
__device__ __forceinline__ void grp4p(u64& qxy, u64& qzw,
                                      u64 cc, u64 ss, u64 nss, u64 umask) {
    u64 t01 = f2fma(cc, qxy, f2mul(nss, qzw));
    u64 t23 = f2fma(cc, qzw, f2mul(ss,  qxy));
    u64 u23 = lswap(t23) ^ umask;
    qxy = f2fma(cc, t01, f2mul(ss,  u23));
    qzw = f2fma(cc, u23, f2mul(nss, t01));
}
// full neuron on 8 amps (two packed groups), R5-proven
__device__ __forceinline__ void neuron8p(u64& xy0, u64& zw0, u64& xy1, u64& zw1,
                                         float2 cs0, float2 cs1) {
    u64 cc0 = bcast(cs0.x), ss0 = bcast(cs0.y), nss0 = ss0 ^ NEGB;
    u64 cc1 = bcast(cs1.x), ss1 = bcast(cs1.y), nss1 = ss1 ^ NEGB;
    grp4p(xy0, zw0, cc0, ss0, nss0, MASKP);
    grp4p(xy1, zw1, cc1, ss1, nss1, MASKP);
    xswapneg(xy0, xy1);
    xswapneg(zw0, zw1);
    grp4p(xy0, zw0, cc0, ss0, nss0, MASKM);
    grp4p(xy1, zw1, cc1, ss1, nss1, MASKM);
}

// RY on bit `bit` of the 8-element u64 register index (no lane crossing)
__device__ __forceinline__ void ry8b(u64 R[8], int bit, float2 cs) {
    u64 cc = bcast(cs.x), ss = bcast(cs.y), nss = ss ^ NEGB;
    #pragma unroll
    for (int k = 0; k < 8; k++) {
        if (!((k >> bit) & 1)) {
            int k1 = k | (1 << bit);
            u64 a = R[k], b2 = R[k1];
            R[k]  = f2fma(cc, a, f2mul(nss, b2));
            R[k1] = f2fma(ss, a, f2mul(cc,  b2));
        }
    }
}

// Neuron pair: neurons targeting amp bits PA, PA-1; thread owns amp bits {PA,PA-1,1,0}
template <int PA>
__device__ __forceinline__ void neuron_pairp(u64* sm,
                                             const float2* __restrict__ tabA,
                                             const float2* __restrict__ tabB,
                                             int t) {
    constexpr int PB = PA - 1;
    constexpr int LB = PB - 2;
    const int low  = t & ((1 << LB) - 1);
    const int high = t >> LB;
    const int gb   = low | (high << (PA - 1));

    const int g00 = gb;
    const int g01 = gb + (1 << (PB - 2));
    const int g10 = gb + (1 << (PA - 2));
    const int g11 = g10 + (1 << (PB - 2));

    u64 a0, b0, a1, b1, a2, b2, a3, b3;
    ld2(sm, g00, a0, b0); ld2(sm, g01, a1, b1);
    ld2(sm, g10, a2, b2); ld2(sm, g11, a3, b3);

    neuron8p(a0, b0, a2, b2, tabA[g00], tabA[g10]);
    neuron8p(a1, b1, a3, b3, tabA[g01], tabA[g11]);
    neuron8p(a0, b0, a1, b1, tabB[g00], tabB[g01]);
    neuron8p(a2, b2, a3, b3, tabB[g10], tabB[g11]);

    st2(sm, g00, a0, b0); st2(sm, g01, a1, b1);
    st2(sm, g10, a2, b2); st2(sm, g11, a3, b3);
}

__global__ void __launch_bounds__(256, 4) sim_kernel(
    const float* __restrict__ psi_in,
    const int*   __restrict__ inp,
    float*       __restrict__ probs_out,
    float*       __restrict__ psi_out)
{
    __shared__ __align__(16) u64 sm[NSTATE / 2];
    __shared__ float red[256];

    const int b = blockIdx.x;
    const int t = threadIdx.x;

    int mask = 0;
    #pragma unroll
    for (int l = 0; l < NIN; l++) mask |= (inp[l] & 1) << (11 - l);

    #pragma unroll
    for (int s = 0; s < STAGES; s++) {
        const float2* ut = &u_tab[s * W_];

        // ---- U-A: RY lanes 0,1,2 (e bits 10,9,8). e = t | (k<<8).
        {
            u64 R[8];
            if (s == 0) {
                const float* in = psi_in + (size_t)b * NSTATE;
                #pragma unroll
                for (int k = 0; k < 8; k++) {
                    int e = t | (k << 8);
                    R[k] = *(const u64*)(in + (((e << 1)) ^ mask));
                }
            } else {
                #pragma unroll
                for (int k = 0; k < 8; k++) R[k] = sm[swE(t | (k << 8))];
            }
            ry8b(R, 2, ut[0]); ry8b(R, 1, ut[1]); ry8b(R, 0, ut[2]);
            #pragma unroll
            for (int k = 0; k < 8; k++) sm[swE(t | (k << 8))] = R[k];
        }
        __syncthreads();

        // ---- U-B: RY lanes 3,4,5 (e bits 7,6,5). e = (t&31)|(k<<5)|((t>>5)<<8).
        {
            const int base = (t & 31) | ((t >> 5) << 8);
            u64 R[8];
            #pragma unroll
            for (int k = 0; k < 8; k++) R[k] = sm[swE(base | (k << 5))];
            ry8b(R, 2, ut[3]); ry8b(R, 1, ut[4]); ry8b(R, 0, ut[5]);
            #pragma unroll
            for (int k = 0; k < 8; k++) sm[swE(base | (k << 5))] = R[k];
        }
        __syncthreads();

        // ---- U-C: RY lanes 6,7,8 (e bits 4,3,2) + lane 9 (e bit 1) via shfl.
        {
            const int base = (t & 3) | ((t >> 2) << 5);
            u64 R[8];
            #pragma unroll
            for (int k = 0; k < 8; k++) R[k] = sm[swE(base | (k << 2))];
            ry8b(R, 2, ut[6]); ry8b(R, 1, ut[7]); ry8b(R, 0, ut[8]);
            // lane 9: partner thread t^2; sign +s for e-bit1==1 (t&2), -s else
            {
                u64 cc = bcast(ut[9].x);
                u64 sp = bcast((t & 2) ? ut[9].y : -ut[9].y);
                #pragma unroll
                for (int k = 0; k < 8; k++) {
                    u64 o = __shfl_xor_sync(0xffffffffu, R[k], 2);
                    R[k] = f2fma(cc, R[k], f2mul(sp, o));
                }
            }
            #pragma unroll
            for (int k = 0; k < 8; k++) sm[swE(base | (k << 2))] = R[k];
        }
        __syncthreads();

        const float2* tb = &g_tab[(s * W_) << 10];

        // ---- neuron pairs (0,1),(2,3),(4,5),(6,7)
        neuron_pairp<11>(sm, tb + (0 << 10), tb + (1 << 10), t); __syncthreads();
        neuron_pairp<9 >(sm, tb + (2 << 10), tb + (3 << 10), t); __syncthreads();
        neuron_pairp<7 >(sm, tb + (4 << 10), tb + (5 << 10), t); __syncthreads();
        neuron_pairp<5 >(sm, tb + (6 << 10), tb + (7 << 10), t); __syncthreads();

        // ---- neurons 8,9 (group bits 1,0): 4 contiguous groups G0..G0+3.
        {
            const float2* tabA = tb + (8 << 10);
            const float2* tabB = tb + (9 << 10);
            const int G0 = t << 2;
            u64 a0, b0, a1, b1, a2, b2, a3, b3;
            ld2(sm, G0,     a0, b0); ld2(sm, G0 + 1, a1, b1);
            ld2(sm, G0 + 2, a2, b2); ld2(sm, G0 + 3, a3, b3);

            neuron8p(a0, b0, a2, b2, tabA[G0],     tabA[G0 + 2]);
            neuron8p(a1, b1, a3, b3, tabA[G0 + 1], tabA[G0 + 3]);
            neuron8p(a0, b0, a1, b1, tabB[G0],     tabB[G0 + 1]);
            neuron8p(a2, b2, a3, b3, tabB[G0 + 2], tabB[G0 + 3]);

            if (s == STAGES - 1) {
                ulonglong2* out2 = (ulonglong2*)(psi_out + (size_t)b * NSTATE);
                out2[G0]     = make_ulonglong2(a0, b0);
                out2[G0 + 1] = make_ulonglong2(a1, b1);
                out2[G0 + 2] = make_ulonglong2(a2, b2);
                out2[G0 + 3] = make_ulonglong2(a3, b3);
                u64 q[8] = {a0, b0, a1, b1, a2, b2, a3, b3};
                float ssq = 0.f;
                #pragma unroll
                for (int j = 0; j < 8; j++) {
                    float2 f = *(float2*)&q[j];
                    ssq += f.x * f.x + f.y * f.y;
                }
                red[t] = ssq;
            } else {
                st2(sm, G0,     a0, b0); st2(sm, G0 + 1, a1, b1);
                st2(sm, G0 + 2, a2, b2); st2(sm, G0 + 3, a3, b3);
            }
        }
        __syncthreads();
    }

    // probs: thread t covers amps 16t..16t+15 -> bucket t>>2
    if (t < 64) {
        probs_out[b * 64 + t] =
            red[4 * t] + red[4 * t + 1] + red[4 * t + 2] + red[4 * t + 3];
    }
}

extern "C" void kernel_launch(void* const* d_in, const int* in_sizes, int n_in,
                              void* d_out, int out_size) {
    const float* psi = (const float*)d_in[0];
    const int*   inp = (const int*)d_in[1];
    const float* uth = (const float*)d_in[2];
    const float* nth = (const float*)d_in[3];
    float* out = (float*)d_out;

    float* probs_out = out;
    float* psi_out   = out + BATCH * 64;

    precompute_kernel<<<(STAGES * W_ * 1024 + 255) / 256, 256>>>(uth, nth);
    sim_kernel<<<BATCH, 256>>>(psi, inp, probs_out, psi_out);
}